// round 1
// baseline (speedup 1.0000x reference)
#include <cuda_runtime.h>
#include <cstdint>

#define B_ 8
#define P_ 64
#define S_ 256
#define D_ 256

// ---------------- device scratch (no allocations allowed) ----------------
__device__ float g_redbuf[B_ * P_ * S_];     // red[b,p,s], 512 KB
__device__ float g_partials[P_ * 16 * 5];    // per-CTA BN partials, each slot written exactly once
__device__ float g_scale[P_];
__device__ float g_bias[P_];

using u64 = unsigned long long;

__device__ __forceinline__ u64 fma2(u64 a, u64 b, u64 c) {
    u64 d;
    asm("fma.rn.f32x2 %0, %1, %2, %3;" : "=l"(d) : "l"(a), "l"(b), "l"(c));
    return d;
}
__device__ __forceinline__ u64 pack2(float lo, float hi) {
    u64 d;
    asm("mov.b64 %0, {%1, %2};" : "=l"(d) : "f"(lo), "f"(hi));
    return d;
}
__device__ __forceinline__ void unpack2(u64 v, float& lo, float& hi) {
    asm("mov.b64 {%0, %1}, %2;" : "=f"(lo), "=f"(hi) : "l"(v));
}

// ---------------- smem layout (floats) ----------------
constexpr int XS_STRIDE = 132;                  // 128 rows + 4 pad (conflict-free column reads)
constexpr int BT_STRIDE = 68;                   // 64 rows + 4 pad
constexpr int OFF_XS    = 0;                    // 256*132 = 33792
constexpr int OFF_BT    = OFF_XS + 256 * XS_STRIDE;     // 33792
constexpr int OFF_REDP  = OFF_BT + 256 * BT_STRIDE;     // 51200 ; 128*17 = 2176
constexpr int OFF_ROWS  = OFF_REDP + 128 * 17;          // 53376
constexpr int OFF_SX2   = OFF_ROWS + 128;               // 53504
constexpr int OFF_REDS  = OFF_SX2 + 128;                // 53632
constexpr int OFF_WSCR  = OFF_REDS + 128;               // 53760
constexpr int SMEM_FLOATS = OFF_WSCR + 8;               // 53768 -> 215072 bytes
constexpr int SMEM_BYTES  = SMEM_FLOATS * 4;

// =====================================================================
// Main kernel: per CTA = (s-tile of 128 rows, p, b).
// Computes red[s] = (1/16) * sum_t w[p,s,t] * (x_s . x_t)
// and the 5 BN partials for this tile. Fully deterministic (no atomics).
// =====================================================================
__global__ void __launch_bounds__(256, 1)
da_main_kernel(const float* __restrict__ x, const float* __restrict__ w)
{
    extern __shared__ float sm[];
    float* XsT  = sm + OFF_XS;     // [k=256][row=128(+pad)]  k-major transposed Xs
    float* BtT  = sm + OFF_BT;     // [k=256][t=64(+pad)]
    float* redp = sm + OFF_REDP;   // [128][17] partial red per tx
    float* rows = sm + OFF_ROWS;   // rowsum_x[s_local]
    float* sx2s = sm + OFF_SX2;    // rowsum_x2[s_local]
    float* reds = sm + OFF_REDS;   // red[s_local]
    float* wscr = sm + OFF_WSCR;   // 8-warp reduction scratch

    const int tid = threadIdx.x;
    const int st  = blockIdx.x;    // 0..1   s-tile
    const int p   = blockIdx.y;    // 0..63
    const int b   = blockIdx.z;    // 0..7
    const int s0  = st * 128;
    const float* xbp = x + (size_t)(b * P_ + p) * (S_ * D_);

    // ---- load Xs (128 x 256) transposed into smem ----
    for (int i = tid; i < 128 * 64; i += 256) {
        int row = i >> 6, c4 = i & 63;
        float4 v = *reinterpret_cast<const float4*>(xbp + (size_t)(s0 + row) * D_ + c4 * 4);
        int k = c4 * 4;
        XsT[(k + 0) * XS_STRIDE + row] = v.x;
        XsT[(k + 1) * XS_STRIDE + row] = v.y;
        XsT[(k + 2) * XS_STRIDE + row] = v.z;
        XsT[(k + 3) * XS_STRIDE + row] = v.w;
    }
    __syncthreads();

    // ---- per-row sum and sum of squares of x (for BN stats) ----
    if (tid < 128) {
        float rs = 0.f, s2 = 0.f;
        #pragma unroll 8
        for (int k = 0; k < 256; ++k) {
            float v = XsT[k * XS_STRIDE + tid];
            rs += v;
            s2 += v * v;
        }
        rows[tid] = rs;
        sx2s[tid] = s2;
    }

    const int ty = tid >> 4;   // 0..15 : 8 s-rows each
    const int tx = tid & 15;   // 0..15 : 4 t-cols each
    u64 red2[4] = {0ull, 0ull, 0ull, 0ull};   // f32x2 pairs over s

    for (int t0 = 0; t0 < 256; t0 += 64) {
        __syncthreads();   // previous BtT consumers done (also covers rowsum pass)
        for (int i = tid; i < 64 * 64; i += 256) {
            int row = i >> 6, c4 = i & 63;
            float4 v = *reinterpret_cast<const float4*>(xbp + (size_t)(t0 + row) * D_ + c4 * 4);
            int k = c4 * 4;
            BtT[(k + 0) * BT_STRIDE + row] = v.x;
            BtT[(k + 1) * BT_STRIDE + row] = v.y;
            BtT[(k + 2) * BT_STRIDE + row] = v.z;
            BtT[(k + 3) * BT_STRIDE + row] = v.w;
        }
        __syncthreads();

        // ---- 8x4 micro-tile GEMM over k, packed f32x2 over s-pairs ----
        u64 c2[4][4];
        #pragma unroll
        for (int i2 = 0; i2 < 4; ++i2)
            #pragma unroll
            for (int j = 0; j < 4; ++j) c2[i2][j] = 0ull;

        const float* xsp = XsT + ty * 8;
        const float* btp = BtT + tx * 4;
        #pragma unroll 4
        for (int k = 0; k < 256; ++k) {
            // a pairs loaded directly as b64 from smem (consecutive s rows)
            u64 ap0 = *reinterpret_cast<const u64*>(xsp + k * XS_STRIDE + 0);
            u64 ap1 = *reinterpret_cast<const u64*>(xsp + k * XS_STRIDE + 2);
            u64 ap2 = *reinterpret_cast<const u64*>(xsp + k * XS_STRIDE + 4);
            u64 ap3 = *reinterpret_cast<const u64*>(xsp + k * XS_STRIDE + 6);
            float4 bb = *reinterpret_cast<const float4*>(btp + k * BT_STRIDE);
            u64 bd0 = pack2(bb.x, bb.x);
            u64 bd1 = pack2(bb.y, bb.y);
            u64 bd2 = pack2(bb.z, bb.z);
            u64 bd3 = pack2(bb.w, bb.w);
            c2[0][0] = fma2(ap0, bd0, c2[0][0]);
            c2[0][1] = fma2(ap0, bd1, c2[0][1]);
            c2[0][2] = fma2(ap0, bd2, c2[0][2]);
            c2[0][3] = fma2(ap0, bd3, c2[0][3]);
            c2[1][0] = fma2(ap1, bd0, c2[1][0]);
            c2[1][1] = fma2(ap1, bd1, c2[1][1]);
            c2[1][2] = fma2(ap1, bd2, c2[1][2]);
            c2[1][3] = fma2(ap1, bd3, c2[1][3]);
            c2[2][0] = fma2(ap2, bd0, c2[2][0]);
            c2[2][1] = fma2(ap2, bd1, c2[2][1]);
            c2[2][2] = fma2(ap2, bd2, c2[2][2]);
            c2[2][3] = fma2(ap2, bd3, c2[2][3]);
            c2[3][0] = fma2(ap3, bd0, c2[3][0]);
            c2[3][1] = fma2(ap3, bd1, c2[3][1]);
            c2[3][2] = fma2(ap3, bd2, c2[3][2]);
            c2[3][3] = fma2(ap3, bd3, c2[3][3]);
        }

        // ---- fold weights into red (per t-tile) ----
        const float* wb = w + (size_t)p * (S_ * S_) + (size_t)t0 + (size_t)tx * 4;
        #pragma unroll
        for (int i2 = 0; i2 < 4; ++i2) {
            int se = s0 + ty * 8 + i2 * 2;
            float4 w0 = *reinterpret_cast<const float4*>(wb + (size_t)(se    ) * 256);
            float4 w1 = *reinterpret_cast<const float4*>(wb + (size_t)(se + 1) * 256);
            red2[i2] = fma2(c2[i2][0], pack2(w0.x, w1.x), red2[i2]);
            red2[i2] = fma2(c2[i2][1], pack2(w0.y, w1.y), red2[i2]);
            red2[i2] = fma2(c2[i2][2], pack2(w0.z, w1.z), red2[i2]);
            red2[i2] = fma2(c2[i2][3], pack2(w0.w, w1.w), red2[i2]);
        }
    }

    // ---- reduce red across tx (deterministic, fixed order) ----
    #pragma unroll
    for (int i2 = 0; i2 < 4; ++i2) {
        float lo, hi;
        unpack2(red2[i2], lo, hi);
        redp[(ty * 8 + i2 * 2    ) * 17 + tx] = lo;
        redp[(ty * 8 + i2 * 2 + 1) * 17 + tx] = hi;
    }
    __syncthreads();
    if (tid < 128) {
        float r = 0.f;
        #pragma unroll
        for (int j = 0; j < 16; ++j) r += redp[tid * 17 + j];
        r *= 0.0625f;   // 1/sqrt(D) = 1/16
        reds[tid] = r;
        g_redbuf[((b * P_ + p) << 8) + s0 + tid] = r;
    }
    __syncthreads();

    // ---- BN partials: sum_x, sum_x2, sum_red, sum_red2, cross ----
    float vals[5] = {0.f, 0.f, 0.f, 0.f, 0.f};
    if (tid < 128) {
        float rs = rows[tid], rd = reds[tid];
        vals[0] = rs;
        vals[1] = sx2s[tid];
        vals[2] = rd;
        vals[3] = rd * rd;
        vals[4] = rd * rs;
    }
    float out5[5];
    #pragma unroll
    for (int q = 0; q < 5; ++q) {
        float v = vals[q];
        #pragma unroll
        for (int o = 16; o; o >>= 1) v += __shfl_xor_sync(0xffffffffu, v, o);
        if ((tid & 31) == 0) wscr[tid >> 5] = v;
        __syncthreads();
        if (tid == 0) {
            float r = 0.f;
            for (int t = 0; t < 8; ++t) r += wscr[t];
            out5[q] = r;
        }
        __syncthreads();
    }
    if (tid == 0) {
        int slot = (p * 16 + (b * 2 + st)) * 5;
        #pragma unroll
        for (int q = 0; q < 5; ++q) g_partials[slot + q] = out5[q];
    }
}

// =====================================================================
// Finalize: fold 16 partials per channel into affine scale/bias.
// sum_y = sum_x + D*sum_red ; sum_y2 = sum_x2 + 2*cross + D*sum_red2
// =====================================================================
__global__ void da_finalize_kernel(const float* __restrict__ gamma,
                                   const float* __restrict__ beta)
{
    int p = threadIdx.x;
    if (p >= P_) return;
    float sx = 0.f, sx2 = 0.f, sr = 0.f, sr2 = 0.f, cr = 0.f;
    for (int c = 0; c < 16; ++c) {
        const float* q = g_partials + (p * 16 + c) * 5;
        sx  += q[0];
        sx2 += q[1];
        sr  += q[2];
        sr2 += q[3];
        cr  += q[4];
    }
    const float N = (float)(B_ * S_ * D_);           // 524288
    float sumy  = sx + (float)D_ * sr;
    float sumy2 = sx2 + 2.f * cr + (float)D_ * sr2;
    float mean = sumy / N;
    float var  = sumy2 / N - mean * mean;
    float sc = gamma[p] * rsqrtf(var + 1e-5f);
    g_scale[p] = sc;
    g_bias[p]  = beta[p] - mean * sc;
}

// =====================================================================
// Epilogue: out = (x + red) * scale[p] + bias[p], float4 streaming.
// =====================================================================
__global__ void da_out_kernel(const float* __restrict__ x, float* __restrict__ out)
{
    int f = blockIdx.x * blockDim.x + threadIdx.x;   // float4 index, exactly 8388608 threads
    int s  = (f >> 6) & 255;
    int bp = f >> 14;               // b*64 + p
    int p  = bp & 63;
    float red = g_redbuf[(bp << 8) | s];
    float sc = g_scale[p];
    float bi = g_bias[p];
    float4 v = reinterpret_cast<const float4*>(x)[f];
    v.x = fmaf(v.x + red, sc, bi);
    v.y = fmaf(v.y + red, sc, bi);
    v.z = fmaf(v.z + red, sc, bi);
    v.w = fmaf(v.w + red, sc, bi);
    reinterpret_cast<float4*>(out)[f] = v;
}

// =====================================================================
extern "C" void kernel_launch(void* const* d_in, const int* in_sizes, int n_in,
                              void* d_out, int out_size)
{
    const float* x     = (const float*)d_in[0];
    const float* w     = (const float*)d_in[1];
    const float* gamma = (const float*)d_in[2];
    const float* beta  = (const float*)d_in[3];
    float* out = (float*)d_out;

    cudaFuncSetAttribute(da_main_kernel,
                         cudaFuncAttributeMaxDynamicSharedMemorySize, SMEM_BYTES);

    dim3 grid(2, P_, B_);
    da_main_kernel<<<grid, 256, SMEM_BYTES>>>(x, w);
    da_finalize_kernel<<<1, 64>>>(gamma, beta);
    da_out_kernel<<<(B_ * P_ * S_ * D_ / 4) / 256, 256>>>(x, out);
}

// round 3
// speedup vs baseline: 1.8128x; 1.8128x over previous
#include <cuda_runtime.h>
#include <cuda_bf16.h>
#include <cstdint>

#define B_ 8
#define P_ 64
#define S_ 256
#define D_ 256

// ---------------- device scratch (zero-init at load; reset each run) ----------------
__device__ float g_partials[P_ * 16 * 5];
__device__ float g_scale[P_];
__device__ float g_bias[P_];
__device__ int   g_cnt[P_];
__device__ int   g_cnt2[P_];
__device__ int   g_flag[P_];

__device__ __forceinline__ uint32_t smem_to_u32(const void* p) {
    uint32_t a;
    asm("{ .reg .u64 t; cvta.to.shared.u64 t, %1; cvt.u32.u64 %0, t; }" : "=r"(a) : "l"(p));
    return a;
}

#define LDSM4(d0, d1, d2, d3, a) \
    asm volatile("ldmatrix.sync.aligned.m8n8.x4.shared.b16 {%0,%1,%2,%3}, [%4];" \
                 : "=r"(d0), "=r"(d1), "=r"(d2), "=r"(d3) : "r"(a))

#define HMMA(c, a0, a1, a2, a3, b0, b1) \
    asm volatile("mma.sync.aligned.m16n8k16.row.col.f32.bf16.bf16.f32 " \
                 "{%0,%1,%2,%3}, {%4,%5,%6,%7}, {%8,%9}, {%0,%1,%2,%3};" \
                 : "+f"((c)[0]), "+f"((c)[1]), "+f"((c)[2]), "+f"((c)[3]) \
                 : "r"(a0), "r"(a1), "r"(a2), "r"(a3), "r"(b0), "r"(b1))

// ---------------- smem layout (bytes) ----------------
constexpr int ROWB      = 144;                       // 64 k-elems *2B + 16B pad (conflict-free ldmatrix)
constexpr int OFF_XS    = 0;                         // fp32 x rows [s0,s0+128): 128*1024 = 131072
constexpr int OFF_BH    = 131072;                    // hi bf16 chunk: 256*144 = 36864
constexpr int OFF_BL    = OFF_BH + 36864;            // lo bf16 chunk
constexpr int SMEM_BYTES = OFF_BL + 36864;           // 204800
// reuse of the BH/BL region after the last mma:
constexpr int OFF_REDP  = OFF_BH;                    // 128*17*4 = 8704
constexpr int OFF_RS    = OFF_REDP + 8704;           // 512
constexpr int OFF_S2    = OFF_RS + 512;              // 512
constexpr int OFF_RED   = OFF_S2 + 512;              // 512
constexpr int OFF_W8    = OFF_RED + 512;             // 32
constexpr int OFF_BC    = OFF_W8 + 32;               // 8

// =====================================================================
__global__ void __launch_bounds__(256, 1)
da_fused_kernel(const float* __restrict__ x, const float* __restrict__ w,
                const float* __restrict__ gamma, const float* __restrict__ beta,
                float* __restrict__ out)
{
    extern __shared__ __align__(16) char sm[];
    const uint32_t smb = smem_to_u32(sm);
    const int tid = threadIdx.x, wid = tid >> 5, lane = tid & 31;
    const int bx = blockIdx.x;                 // 0..15 = b*2 + st
    const int b = bx >> 1, st = bx & 1;
    const int p = blockIdx.y;
    const int s0 = st * 128;
    const float* xbp = x + (size_t)(b * P_ + p) * (S_ * D_);

    const int warp_m = wid >> 2;   // 0..1 : 64 m-rows
    const int warp_n = wid & 3;    // 0..3 : 64 n-cols

    // accumulators: 4 m-frags x 8 n-frags x 4 f32
    float acc[4][8][4];
    #pragma unroll
    for (int mi = 0; mi < 4; ++mi)
        #pragma unroll
        for (int nf = 0; nf < 8; ++nf)
            #pragma unroll
            for (int q = 0; q < 4; ++q) acc[mi][nf][q] = 0.f;

    // ldmatrix per-lane addressing (identical pattern for A and B operands)
    const uint32_t lrow = lane & 15;
    const uint32_t lcol = (lane >> 4) * 16;    // bytes: k-half select
    uint32_t aaddr[4], baddr[4];
    #pragma unroll
    for (int mi = 0; mi < 4; ++mi)
        aaddr[mi] = smb + OFF_BH + (uint32_t)(s0 + warp_m * 64 + mi * 16 + lrow) * ROWB + lcol;
    #pragma unroll
    for (int nj = 0; nj < 4; ++nj)
        baddr[nj] = smb + OFF_BH + (uint32_t)(warp_n * 64 + nj * 16 + lrow) * ROWB + lcol;

    const int rbase = tid >> 4;    // 0..15
    const int c4    = tid & 15;    // float4 col in 64-k chunk

    // ================= k-chunk loop: convert + 3-pass MMA =================
    for (int kc = 0; kc < 4; ++kc) {
        __syncthreads();   // chunk buffers free
        const float* xc = xbp + kc * 64 + c4 * 4;
        #pragma unroll
        for (int j = 0; j < 16; ++j) {
            int row = rbase + 16 * j;
            float4 v = *reinterpret_cast<const float4*>(xc + (size_t)row * D_);
            __nv_bfloat162 h01 = __floats2bfloat162_rn(v.x, v.y);
            __nv_bfloat162 h23 = __floats2bfloat162_rn(v.z, v.w);
            __nv_bfloat162 l01 = __floats2bfloat162_rn(v.x - __low2float(h01),
                                                       v.y - __high2float(h01));
            __nv_bfloat162 l23 = __floats2bfloat162_rn(v.z - __low2float(h23),
                                                       v.w - __high2float(h23));
            uint32_t off = (uint32_t)row * ROWB + (uint32_t)c4 * 8;
            *reinterpret_cast<uint2*>(sm + OFF_BH + off) =
                make_uint2(*reinterpret_cast<uint32_t*>(&h01), *reinterpret_cast<uint32_t*>(&h23));
            *reinterpret_cast<uint2*>(sm + OFF_BL + off) =
                make_uint2(*reinterpret_cast<uint32_t*>(&l01), *reinterpret_cast<uint32_t*>(&l23));
            int rl = row - s0;
            if (rl >= 0 && rl < 128)
                *reinterpret_cast<float4*>(sm + OFF_XS + (size_t)rl * 1024 + kc * 256 + c4 * 16) = v;
        }
        __syncthreads();

        #pragma unroll
        for (int ks = 0; ks < 4; ++ks) {
            const uint32_t ko = (uint32_t)ks * 32;
            uint32_t ah[4][4], al[4][4], bb[4][4];
            #pragma unroll
            for (int mi = 0; mi < 4; ++mi) {
                LDSM4(ah[mi][0], ah[mi][1], ah[mi][2], ah[mi][3], aaddr[mi] + ko);
                LDSM4(al[mi][0], al[mi][1], al[mi][2], al[mi][3], aaddr[mi] + ko + 36864u);
            }
            #pragma unroll
            for (int nj = 0; nj < 4; ++nj)
                LDSM4(bb[nj][0], bb[nj][1], bb[nj][2], bb[nj][3], baddr[nj] + ko);
            // hi*hi and lo*hi
            #pragma unroll
            for (int mi = 0; mi < 4; ++mi)
                #pragma unroll
                for (int nf = 0; nf < 8; ++nf) {
                    HMMA(acc[mi][nf], ah[mi][0], ah[mi][1], ah[mi][2], ah[mi][3],
                         bb[nf >> 1][nf & 1], bb[nf >> 1][2 + (nf & 1)]);
                    HMMA(acc[mi][nf], al[mi][0], al[mi][1], al[mi][2], al[mi][3],
                         bb[nf >> 1][nf & 1], bb[nf >> 1][2 + (nf & 1)]);
                }
            // hi*lo
            #pragma unroll
            for (int nj = 0; nj < 4; ++nj)
                LDSM4(bb[nj][0], bb[nj][1], bb[nj][2], bb[nj][3], baddr[nj] + ko + 36864u);
            #pragma unroll
            for (int mi = 0; mi < 4; ++mi)
                #pragma unroll
                for (int nf = 0; nf < 8; ++nf)
                    HMMA(acc[mi][nf], ah[mi][0], ah[mi][1], ah[mi][2], ah[mi][3],
                         bb[nf >> 1][nf & 1], bb[nf >> 1][2 + (nf & 1)]);
        }
    }

    __syncthreads();   // B buffers now reusable

    // ================= fold W from global into per-row partials =================
    float* redp = reinterpret_cast<float*>(sm + OFF_REDP);
    const float* wp = w + ((size_t)p << 16);
    #pragma unroll
    for (int mi = 0; mi < 4; ++mi)
        #pragma unroll
        for (int half = 0; half < 2; ++half) {
            int rl = warp_m * 64 + mi * 16 + (lane >> 2) + half * 8;
            const float* wr = wp + (size_t)(s0 + rl) * 256 + warp_n * 64 + (lane & 3) * 2;
            float part = 0.f;
            #pragma unroll
            for (int nf = 0; nf < 8; ++nf) {
                float2 wv = __ldg(reinterpret_cast<const float2*>(wr + nf * 8));
                part = fmaf(acc[mi][nf][half * 2 + 0], wv.x, part);
                part = fmaf(acc[mi][nf][half * 2 + 1], wv.y, part);
            }
            redp[rl * 17 + warp_n * 4 + (lane & 3)] = part;
        }

    // ================= per-row x sums from xsave (warp per 16 rows) =================
    float* xs   = reinterpret_cast<float*>(sm + OFF_XS);
    float* rssm = reinterpret_cast<float*>(sm + OFF_RS);
    float* s2sm = reinterpret_cast<float*>(sm + OFF_S2);
    #pragma unroll
    for (int j = 0; j < 16; ++j) {
        int r = wid * 16 + j;
        float4 v0 = *reinterpret_cast<const float4*>(xs + r * 256 + lane * 4);
        float4 v1 = *reinterpret_cast<const float4*>(xs + r * 256 + 128 + lane * 4);
        float rsv = v0.x + v0.y + v0.z + v0.w + v1.x + v1.y + v1.z + v1.w;
        float s2v = v0.x * v0.x + v0.y * v0.y + v0.z * v0.z + v0.w * v0.w
                  + v1.x * v1.x + v1.y * v1.y + v1.z * v1.z + v1.w * v1.w;
        #pragma unroll
        for (int o = 16; o; o >>= 1) {
            rsv += __shfl_xor_sync(0xffffffffu, rsv, o);
            s2v += __shfl_xor_sync(0xffffffffu, s2v, o);
        }
        if (lane == 0) { rssm[r] = rsv; s2sm[r] = s2v; }
    }
    __syncthreads();

    // ================= finalize red + BN partials =================
    float* redsm = reinterpret_cast<float*>(sm + OFF_RED);
    float vals[5] = {0.f, 0.f, 0.f, 0.f, 0.f};
    if (tid < 128) {
        float rsum = 0.f;
        #pragma unroll
        for (int l = 0; l < 16; ++l) rsum += redp[tid * 17 + l];
        float red = rsum * 0.0625f;    // 1/sqrt(256)
        redsm[tid] = red;
        float xr = rssm[tid], x2 = s2sm[tid];
        vals[0] = xr; vals[1] = x2; vals[2] = red; vals[3] = red * red; vals[4] = red * xr;
    }
    float* w8 = reinterpret_cast<float*>(sm + OFF_W8);
    float out5[5];
    #pragma unroll
    for (int q = 0; q < 5; ++q) {
        float v = vals[q];
        #pragma unroll
        for (int o = 16; o; o >>= 1) v += __shfl_xor_sync(0xffffffffu, v, o);
        if (lane == 0) w8[wid] = v;
        __syncthreads();
        if (tid == 0) {
            float r = 0.f;
            for (int t = 0; t < 8; ++t) r += w8[t];
            out5[q] = r;
        }
        __syncthreads();
    }

    // ================= cross-CTA BN handshake (16 CTAs per channel) =================
    float* bc = reinterpret_cast<float*>(sm + OFF_BC);
    if (tid == 0) {
        int slot = (p * 16 + bx) * 5;
        #pragma unroll
        for (int q = 0; q < 5; ++q) g_partials[slot + q] = out5[q];
        __threadfence();
        int o = atomicAdd(&g_cnt[p], 1);
        if (o == 15) {
            __threadfence();
            float sx = 0.f, sx2 = 0.f, sr = 0.f, sr2 = 0.f, cr = 0.f;
            for (int c = 0; c < 16; ++c) {
                const float* q = g_partials + (p * 16 + c) * 5;
                sx += q[0]; sx2 += q[1]; sr += q[2]; sr2 += q[3]; cr += q[4];
            }
            const float N = (float)(B_ * S_ * D_);
            float sumy  = sx + (float)D_ * sr;
            float sumy2 = sx2 + 2.f * cr + (float)D_ * sr2;
            float mean = sumy / N;
            float var  = sumy2 / N - mean * mean;
            float sc = __ldg(gamma + p) * rsqrtf(var + 1e-5f);
            g_scale[p] = sc;
            g_bias[p]  = __ldg(beta + p) - mean * sc;
            __threadfence();
            atomicExch(&g_flag[p], 1);
        }
        volatile int* fl = (volatile int*)&g_flag[p];
        while (*fl == 0) __nanosleep(64);
        __threadfence();
        bc[0] = g_scale[p];
        bc[1] = g_bias[p];
        int o2 = atomicAdd(&g_cnt2[p], 1);
        if (o2 == 15) {        // all 16 CTAs have consumed scale/bias: reset for next replay
            g_flag[p] = 0; g_cnt[p] = 0; g_cnt2[p] = 0;
        }
    }
    __syncthreads();
    const float sc = bc[0], bi = bc[1];

    // ================= output: out = (x + red) * sc + bi =================
    float* ob = out + ((size_t)(b * P_ + p) << 16) + (size_t)s0 * 256;
    #pragma unroll
    for (int j = 0; j < 16; ++j) {
        int r = wid * 16 + j;
        float red = redsm[r];
        #pragma unroll
        for (int it = 0; it < 2; ++it) {
            float4 v = *reinterpret_cast<const float4*>(xs + r * 256 + it * 128 + lane * 4);
            v.x = fmaf(v.x + red, sc, bi);
            v.y = fmaf(v.y + red, sc, bi);
            v.z = fmaf(v.z + red, sc, bi);
            v.w = fmaf(v.w + red, sc, bi);
            *reinterpret_cast<float4*>(ob + (size_t)r * 256 + it * 128 + lane * 4) = v;
        }
    }
}

// =====================================================================
extern "C" void kernel_launch(void* const* d_in, const int* in_sizes, int n_in,
                              void* d_out, int out_size)
{
    const float* x     = (const float*)d_in[0];
    const float* w     = (const float*)d_in[1];
    const float* gamma = (const float*)d_in[2];
    const float* beta  = (const float*)d_in[3];
    float* out = (float*)d_out;

    cudaFuncSetAttribute(da_fused_kernel,
                         cudaFuncAttributeMaxDynamicSharedMemorySize, SMEM_BYTES);

    dim3 grid(16, P_);   // blockIdx.x = b*2+st (channel CTAs contiguous), blockIdx.y = p
    da_fused_kernel<<<grid, 256, SMEM_BYTES>>>(x, w, gamma, beta, out);
}